// round 4
// baseline (speedup 1.0000x reference)
#include <cuda_runtime.h>
#include <cstdint>

#define B_   128
#define N_   197
#define C_   768
#define H_   12
#define HD_  64
#define M_   (B_*N_)      // 25216
#define NN_  (N_*N_)      // 38809

// ---------------- scratch (device globals; no allocation allowed) -----------
__device__ float g_q[B_*H_*N_*HD_];      // [B,H,N,64]
__device__ float g_k[B_*H_*N_*HD_];
__device__ float g_v[B_*H_*N_*HD_];
__device__ float g_att[M_*C_];           // [B*N, 768] attention output
__device__ float g_relbias[H_*NN_];      // [H,N,N]

// ---------------- helpers ---------------------------------------------------
__device__ __forceinline__ void cp16(float* smem_dst, const float* gsrc) {
    uint32_t s = (uint32_t)__cvta_generic_to_shared(smem_dst);
    asm volatile("cp.async.cg.shared.global [%0], [%1], 16;" :: "r"(s), "l"(gsrc));
}

__device__ __forceinline__ uint32_t f2tf(float x) {
    uint32_t r;
    asm("cvt.rna.tf32.f32 %0, %1;" : "=r"(r) : "f"(x));
    return r;
}
// split fp32 into hi (tf32) + lo (tf32 of residual); ah+al ~ 20-bit mantissa
__device__ __forceinline__ void tf_split(float x, uint32_t& hi, uint32_t& lo) {
    hi = f2tf(x);
    lo = f2tf(x - __uint_as_float(hi));
}

__device__ __forceinline__ void mma_tf32(float c[4], const uint32_t a[4],
                                         uint32_t b0, uint32_t b1) {
    asm volatile(
        "mma.sync.aligned.m16n8k8.row.col.f32.tf32.tf32.f32 "
        "{%0,%1,%2,%3}, {%4,%5,%6,%7}, {%8,%9}, {%0,%1,%2,%3};\n"
        : "+f"(c[0]), "+f"(c[1]), "+f"(c[2]), "+f"(c[3])
        : "r"(a[0]), "r"(a[1]), "r"(a[2]), "r"(a[3]), "r"(b0), "r"(b1));
}

// 3xTF32: c += a*b with ~fp32 accuracy. ah,al per-fragment; bh/bl pairs.
__device__ __forceinline__ void mma3(float c[4], const uint32_t ah[4],
                                     const uint32_t al[4],
                                     uint32_t bh0, uint32_t bh1,
                                     uint32_t bl0, uint32_t bl1) {
    mma_tf32(c, ah, bh0, bh1);
    mma_tf32(c, al, bh0, bh1);
    mma_tf32(c, ah, bl0, bl1);
}

// ---------------- rel-bias gather -------------------------------------------
__global__ void relbias_kernel(const float* __restrict__ table,
                               const int* __restrict__ idx) {
    int i = blockIdx.x * 256 + threadIdx.x;
    if (i < NN_) {
        int id = idx[i];
        #pragma unroll
        for (int h = 0; h < H_; h++)
            g_relbias[h * NN_ + i] = table[id * H_ + h];
    }
}

// ---------------- TN GEMM (A[M,768] row-major, W[N,768] row-major) ----------
// MODE 0: QKV (N=2304). epilogue: +bias, q-scale, scatter into g_q/g_k/g_v.
// MODE 1: proj (N=768), A = g_att. epilogue: +proj_b, write d_out.
#define SKW 20  // smem stride (floats): conflict-free for the mma frag pattern

template<int MODE>
__global__ void __launch_bounds__(256) gemm_tn(const float* __restrict__ Am,
                                               const float* __restrict__ Wm,
                                               const float* __restrict__ bq,
                                               const float* __restrict__ bv,
                                               float* __restrict__ outp) {
    __shared__ float As[2][128 * SKW];
    __shared__ float Bs[2][128 * SKW];

    const int bn = blockIdx.x, bm = blockIdx.y;
    const int tid = threadIdx.x, lane = tid & 31, warp = tid >> 5;
    const int g = lane >> 2, tg = lane & 3;
    const int wm = warp >> 1, wn = warp & 1;

    const float* Abase = (MODE == 1) ? (const float*)g_att : Am;
    const float* Ag = Abase + (size_t)bm * 128 * 768;
    const float* Wg = Wm + (size_t)bn * 128 * 768;

    float acc[2][8][4];
    #pragma unroll
    for (int i = 0; i < 2; i++)
        #pragma unroll
        for (int j = 0; j < 8; j++)
            #pragma unroll
            for (int l = 0; l < 4; l++) acc[i][j][l] = 0.f;

    // prologue: tile 0
    {
        #pragma unroll
        for (int ee = 0; ee < 2; ee++) {
            int e = tid + ee * 256;
            int row = e >> 2, c4 = (e & 3) << 2;
            cp16(&As[0][row * SKW + c4], Ag + (size_t)row * 768 + c4);
        }
        #pragma unroll
        for (int ee = 0; ee < 2; ee++) {
            int e = tid + ee * 256;
            int row = e >> 2, c4 = (e & 3) << 2;
            cp16(&Bs[0][row * SKW + c4], Wg + (size_t)row * 768 + c4);
        }
        asm volatile("cp.async.commit_group;");
    }

    for (int kt = 0; kt < 48; kt++) {
        int cur = kt & 1;
        if (kt + 1 < 48) {
            int nxt = cur ^ 1;
            int koff = (kt + 1) * 16;
            #pragma unroll
            for (int ee = 0; ee < 2; ee++) {
                int e = tid + ee * 256;
                int row = e >> 2, c4 = (e & 3) << 2;
                cp16(&As[nxt][row * SKW + c4], Ag + (size_t)row * 768 + koff + c4);
            }
            #pragma unroll
            for (int ee = 0; ee < 2; ee++) {
                int e = tid + ee * 256;
                int row = e >> 2, c4 = (e & 3) << 2;
                cp16(&Bs[nxt][row * SKW + c4], Wg + (size_t)row * 768 + koff + c4);
            }
        }
        asm volatile("cp.async.commit_group;");
        asm volatile("cp.async.wait_group 1;");
        __syncthreads();

        const float* A = As[cur];
        const float* Bp = Bs[cur];
        #pragma unroll
        for (int ks = 0; ks < 2; ks++) {
            int k0 = ks * 8;
            uint32_t ah[2][4], al[2][4];
            #pragma unroll
            for (int mt = 0; mt < 2; mt++) {
                int r = wm * 32 + mt * 16 + g;
                tf_split(A[r * SKW + k0 + tg],           ah[mt][0], al[mt][0]);
                tf_split(A[(r + 8) * SKW + k0 + tg],     ah[mt][1], al[mt][1]);
                tf_split(A[r * SKW + k0 + tg + 4],       ah[mt][2], al[mt][2]);
                tf_split(A[(r + 8) * SKW + k0 + tg + 4], ah[mt][3], al[mt][3]);
            }
            #pragma unroll
            for (int nt = 0; nt < 8; nt++) {
                int nc = wn * 64 + nt * 8 + g;
                uint32_t bh0, bl0, bh1, bl1;
                tf_split(Bp[nc * SKW + k0 + tg],     bh0, bl0);
                tf_split(Bp[nc * SKW + k0 + tg + 4], bh1, bl1);
                mma3(acc[0][nt], ah[0], al[0], bh0, bh1, bl0, bl1);
                mma3(acc[1][nt], ah[1], al[1], bh0, bh1, bl0, bl1);
            }
        }
        __syncthreads();
    }

    // ---------------- epilogue ----------------
    if (MODE == 0) {
        const int which = bn / 6;                    // 0=q 1=k 2=v
        const int h = (bn % 6) * 2 + wn;             // head (constant per warp)
        float* dst = (which == 0) ? g_q : (which == 1) ? g_k : g_v;
        #pragma unroll
        for (int mt = 0; mt < 2; mt++)
            #pragma unroll
            for (int hf = 0; hf < 2; hf++) {
                int r = bm * 128 + wm * 32 + mt * 16 + g + hf * 8;
                int bb = r / N_, np = r - bb * N_;
                float* rowp = dst + ((size_t)(bb * H_ + h) * N_ + np) * HD_;
                #pragma unroll
                for (int nt = 0; nt < 8; nt++) {
                    int d0 = nt * 8 + 2 * tg;
                    float a0 = 0.f, a1 = 0.f;
                    if (which == 0) { a0 = bq[h * 64 + d0]; a1 = bq[h * 64 + d0 + 1]; }
                    else if (which == 2) { a0 = bv[h * 64 + d0]; a1 = bv[h * 64 + d0 + 1]; }
                    float v0 = acc[mt][nt][hf * 2] + a0;
                    float v1 = acc[mt][nt][hf * 2 + 1] + a1;
                    if (which == 0) { v0 *= 0.125f; v1 *= 0.125f; } // hd^-0.5
                    rowp[d0] = v0; rowp[d0 + 1] = v1;
                }
            }
    } else {
        #pragma unroll
        for (int mt = 0; mt < 2; mt++)
            #pragma unroll
            for (int hf = 0; hf < 2; hf++) {
                int r = bm * 128 + wm * 32 + mt * 16 + g + hf * 8;
                float* rowp = outp + (size_t)r * 768;
                #pragma unroll
                for (int nt = 0; nt < 8; nt++) {
                    int colg = bn * 128 + wn * 64 + nt * 8 + 2 * tg;
                    rowp[colg] = acc[mt][nt][hf * 2] + bq[colg];
                    rowp[colg + 1] = acc[mt][nt][hf * 2 + 1] + bq[colg + 1];
                }
            }
    }
}

// ---------------- fused attention per (row-chunk, head, batch) --------------
// smem (floats): q_s[128][68] | k_s[208][68] (later vT[64][212]) | S[128][212]
#define QS_STRIDE 68
#define S_STRIDE  212
#define SM_QS  0
#define SM_KS  (128 * QS_STRIDE)               // 8704
#define SM_S   (SM_KS + 208 * QS_STRIDE)       // 22848
#define SM_FLOATS (SM_S + 128 * S_STRIDE)      // 49984 -> 199936 B

__global__ void __launch_bounds__(256) attn_kernel() {
    extern __shared__ float sm[];
    float* q_s = sm + SM_QS;
    float* k_s = sm + SM_KS;
    float* S   = sm + SM_S;

    const int tid = threadIdx.x, lane = tid & 31, warp = tid >> 5;
    const int g = lane >> 2, tg = lane & 3;
    const int wm = warp >> 1, wn = warp & 1;
    const int r0 = blockIdx.x * 128;
    const int h = blockIdx.y, b = blockIdx.z;

    const float* qg = g_q + (size_t)(b * H_ + h) * N_ * HD_;
    const float* kg = g_k + (size_t)(b * H_ + h) * N_ * HD_;
    const float* vg = g_v + (size_t)(b * H_ + h) * N_ * HD_;

    // load q rows [r0, r0+128) (zero-pad past N), k rows [0,208) (zero-pad)
    for (int e = tid; e < 128 * 16; e += 256) {
        int row = e >> 4, c4 = (e & 15) << 2;
        float4 val = make_float4(0.f, 0.f, 0.f, 0.f);
        int gr = r0 + row;
        if (gr < N_) val = *(const float4*)(qg + (size_t)gr * HD_ + c4);
        *(float4*)(q_s + row * QS_STRIDE + c4) = val;
    }
    for (int e = tid; e < 208 * 16; e += 256) {
        int row = e >> 4, c4 = (e & 15) << 2;
        float4 val = make_float4(0.f, 0.f, 0.f, 0.f);
        if (row < N_) val = *(const float4*)(kg + (size_t)row * HD_ + c4);
        *(float4*)(k_s + row * QS_STRIDE + c4) = val;
    }
    __syncthreads();

    // ---- S = q . k^T (warp tile 32 x 104, 13 n-tiles) ----
    float cc[2][13][4];
    #pragma unroll
    for (int i = 0; i < 2; i++)
        #pragma unroll
        for (int j = 0; j < 13; j++)
            #pragma unroll
            for (int l = 0; l < 4; l++) cc[i][j][l] = 0.f;

    {
        const float* A = q_s;
        const float* Bp = k_s;
        #pragma unroll
        for (int ks = 0; ks < 8; ks++) {
            int k0 = ks * 8;
            uint32_t ah[2][4], al[2][4];
            #pragma unroll
            for (int mt = 0; mt < 2; mt++) {
                int r = wm * 32 + mt * 16 + g;
                tf_split(A[r * QS_STRIDE + k0 + tg],           ah[mt][0], al[mt][0]);
                tf_split(A[(r + 8) * QS_STRIDE + k0 + tg],     ah[mt][1], al[mt][1]);
                tf_split(A[r * QS_STRIDE + k0 + tg + 4],       ah[mt][2], al[mt][2]);
                tf_split(A[(r + 8) * QS_STRIDE + k0 + tg + 4], ah[mt][3], al[mt][3]);
            }
            #pragma unroll
            for (int nt = 0; nt < 13; nt++) {
                int nc = wn * 104 + nt * 8 + g;
                uint32_t bh0, bl0, bh1, bl1;
                tf_split(Bp[nc * QS_STRIDE + k0 + tg],     bh0, bl0);
                tf_split(Bp[nc * QS_STRIDE + k0 + tg + 4], bh1, bl1);
                mma3(cc[0][nt], ah[0], al[0], bh0, bh1, bl0, bl1);
                mma3(cc[1][nt], ah[1], al[1], bh0, bh1, bl0, bl1);
            }
        }
    }

    // write S (+rel bias); pad cols to 0
    #pragma unroll
    for (int mt = 0; mt < 2; mt++)
        #pragma unroll
        for (int hf = 0; hf < 2; hf++) {
            int rl = wm * 32 + mt * 16 + g + hf * 8;
            int ig = r0 + rl;
            const float* rb = g_relbias + (size_t)h * NN_ + (size_t)min(ig, N_ - 1) * N_;
            #pragma unroll
            for (int nt = 0; nt < 13; nt++) {
                int j0 = wn * 104 + nt * 8 + 2 * tg;
                float v0 = (j0 < N_)     ? cc[mt][nt][hf * 2]     + rb[j0]     : 0.f;
                float v1 = (j0 + 1 < N_) ? cc[mt][nt][hf * 2 + 1] + rb[j0 + 1] : 0.f;
                S[rl * S_STRIDE + j0] = v0;
                S[rl * S_STRIDE + j0 + 1] = v1;
            }
        }
    __syncthreads();  // all k_s reads done -> region reusable as vT

    // vT[d][j] into old k_s region, zero pad cols [197,208)
    float* vT = k_s;
    for (int e = tid; e < N_ * 16; e += 256) {
        int j = e >> 4, d4 = (e & 15) << 2;
        float4 val = *(const float4*)(vg + (size_t)j * HD_ + d4);
        vT[(d4 + 0) * S_STRIDE + j] = val.x;
        vT[(d4 + 1) * S_STRIDE + j] = val.y;
        vT[(d4 + 2) * S_STRIDE + j] = val.z;
        vT[(d4 + 3) * S_STRIDE + j] = val.w;
    }
    for (int e = tid; e < 64 * 11; e += 256) {
        int d = e / 11, j = N_ + (e % 11);
        vT[d * S_STRIDE + j] = 0.f;
    }

    // softmax: 16 rows per warp, lane-parallel over columns
    for (int rr = 0; rr < 16; rr++) {
        int row = warp * 16 + rr;
        float* Sr = S + row * S_STRIDE;
        float mx = -1e30f;
        for (int j = lane; j < N_; j += 32) mx = fmaxf(mx, Sr[j]);
        #pragma unroll
        for (int o = 16; o; o >>= 1) mx = fmaxf(mx, __shfl_xor_sync(0xffffffffu, mx, o));
        float sum = 0.f;
        for (int j = lane; j < N_; j += 32) {
            float e = __expf(Sr[j] - mx);
            Sr[j] = e; sum += e;
        }
        #pragma unroll
        for (int o = 16; o; o >>= 1) sum += __shfl_xor_sync(0xffffffffu, sum, o);
        float inv = 1.f / sum;
        for (int j = lane; j < N_; j += 32) Sr[j] *= inv;
        for (int j = N_ + lane; j < 208; j += 32) Sr[j] = 0.f;
    }
    __syncthreads();

    // ---- O = S . v (warp tile 32 x 32, K padded to 208) ----
    float oo[2][4][4];
    #pragma unroll
    for (int i = 0; i < 2; i++)
        #pragma unroll
        for (int j = 0; j < 4; j++)
            #pragma unroll
            for (int l = 0; l < 4; l++) oo[i][j][l] = 0.f;

    {
        const float* A = S;
        const float* Bp = vT;
        #pragma unroll 2
        for (int ks = 0; ks < 26; ks++) {
            int k0 = ks * 8;
            uint32_t ah[2][4], al[2][4];
            #pragma unroll
            for (int mt = 0; mt < 2; mt++) {
                int r = wm * 32 + mt * 16 + g;
                tf_split(A[r * S_STRIDE + k0 + tg],           ah[mt][0], al[mt][0]);
                tf_split(A[(r + 8) * S_STRIDE + k0 + tg],     ah[mt][1], al[mt][1]);
                tf_split(A[r * S_STRIDE + k0 + tg + 4],       ah[mt][2], al[mt][2]);
                tf_split(A[(r + 8) * S_STRIDE + k0 + tg + 4], ah[mt][3], al[mt][3]);
            }
            #pragma unroll
            for (int nt = 0; nt < 4; nt++) {
                int nc = wn * 32 + nt * 8 + g;
                uint32_t bh0, bl0, bh1, bl1;
                tf_split(Bp[nc * S_STRIDE + k0 + tg],     bh0, bl0);
                tf_split(Bp[nc * S_STRIDE + k0 + tg + 4], bh1, bl1);
                mma3(oo[0][nt], ah[0], al[0], bh0, bh1, bl0, bl1);
                mma3(oo[1][nt], ah[1], al[1], bh0, bh1, bl0, bl1);
            }
        }
    }

    // write [B,N,C] layout for the projection GEMM
    #pragma unroll
    for (int mt = 0; mt < 2; mt++)
        #pragma unroll
        for (int hf = 0; hf < 2; hf++) {
            int rl = wm * 32 + mt * 16 + g + hf * 8;
            int ig = r0 + rl;
            if (ig < N_) {
                float* op = g_att + ((size_t)b * N_ + ig) * C_ + h * HD_;
                #pragma unroll
                for (int nt = 0; nt < 4; nt++) {
                    int d0 = wn * 32 + nt * 8 + 2 * tg;
                    op[d0] = oo[mt][nt][hf * 2];
                    op[d0 + 1] = oo[mt][nt][hf * 2 + 1];
                }
            }
        }
}

// ---------------- launch ----------------------------------------------------
extern "C" void kernel_launch(void* const* d_in, const int* in_sizes, int n_in,
                              void* d_out, int out_size) {
    const float* x       = (const float*)d_in[0];
    const float* qkv_w   = (const float*)d_in[1];
    const float* q_bias  = (const float*)d_in[2];
    const float* v_bias  = (const float*)d_in[3];
    const float* table   = (const float*)d_in[4];
    const float* proj_w  = (const float*)d_in[5];
    const float* proj_b  = (const float*)d_in[6];
    const int*   rel_idx = (const int*)d_in[7];
    float* out = (float*)d_out;

    relbias_kernel<<<(NN_ + 255) / 256, 256>>>(table, rel_idx);
    gemm_tn<0><<<dim3(18, 197), 256>>>(x, qkv_w, q_bias, v_bias, nullptr);

    cudaFuncSetAttribute(attn_kernel, cudaFuncAttributeMaxDynamicSharedMemorySize,
                         SM_FLOATS * 4);
    attn_kernel<<<dim3(2, H_, B_), 256, SM_FLOATS * 4>>>();

    gemm_tn<1><<<dim3(6, 197), 256>>>(nullptr, proj_w, proj_b, nullptr, out);
}

// round 6
// speedup vs baseline: 1.6033x; 1.6033x over previous
#include <cuda_runtime.h>
#include <cuda_bf16.h>
#include <cstdint>

#define B_   128
#define N_   197
#define C_   768
#define H_   12
#define HD_  64
#define M_   (B_*N_)      // 25216
#define NN_  (N_*N_)      // 38809
#define PL_  (B_*H_*N_*HD_)   // 19365888 elems per plane

// ---------------- scratch (device globals; no allocation allowed) -----------
__device__ float g_relbias[H_*NN_];                       // [H,N,N]
__device__ __nv_bfloat16 g_qh[PL_], g_ql[PL_];            // q split [B,H,N,64]
__device__ __nv_bfloat16 g_kh[PL_], g_kl[PL_];
__device__ __nv_bfloat16 g_vh[PL_], g_vl[PL_];
__device__ __nv_bfloat16 g_x_hi[M_*C_],  g_x_lo[M_*C_];   // x split
__device__ __nv_bfloat16 g_att_hi[M_*C_], g_att_lo[M_*C_];
__device__ __nv_bfloat16 g_wqkv_hi[3*C_*C_], g_wqkv_lo[3*C_*C_];
__device__ __nv_bfloat16 g_wp_hi[C_*C_],  g_wp_lo[C_*C_];

// ---------------- helpers ---------------------------------------------------
__device__ __forceinline__ void cp16(uint32_t smem_dst, const void* gsrc) {
    asm volatile("cp.async.cg.shared.global [%0], [%1], 16;" :: "r"(smem_dst), "l"(gsrc));
}
__device__ __forceinline__ uint32_t sm_u32(const void* p) {
    uint32_t a;
    asm("{ .reg .u64 t; cvta.to.shared.u64 t, %1; cvt.u32.u64 %0, t; }" : "=r"(a) : "l"(p));
    return a;
}
// bf16 mma m16n8k16 (row.col), fp32 accum
__device__ __forceinline__ void mma_bf16(float c[4], const uint32_t a[4],
                                         uint32_t b0, uint32_t b1) {
    asm volatile(
        "mma.sync.aligned.m16n8k16.row.col.f32.bf16.bf16.f32 "
        "{%0,%1,%2,%3}, {%4,%5,%6,%7}, {%8,%9}, {%0,%1,%2,%3};\n"
        : "+f"(c[0]), "+f"(c[1]), "+f"(c[2]), "+f"(c[3])
        : "r"(a[0]), "r"(a[1]), "r"(a[2]), "r"(a[3]), "r"(b0), "r"(b1));
}
__device__ __forceinline__ void mma3(float c[4], const uint32_t ah[4],
                                     const uint32_t al[4],
                                     uint32_t bh0, uint32_t bh1,
                                     uint32_t bl0, uint32_t bl1) {
    mma_bf16(c, ah, bh0, bh1);
    mma_bf16(c, al, bh0, bh1);
    mma_bf16(c, ah, bl0, bl1);
}
// split two fp32 into packed bf16x2 hi + bf16x2 lo (f0 -> low half)
__device__ __forceinline__ void pack_split2(float f0, float f1,
                                            uint32_t& h, uint32_t& l) {
    asm("cvt.rn.bf16x2.f32 %0, %1, %2;" : "=r"(h) : "f"(f1), "f"(f0));
    float g1 = __uint_as_float(h & 0xffff0000u);
    float g0 = __uint_as_float(h << 16);
    asm("cvt.rn.bf16x2.f32 %0, %1, %2;" : "=r"(l) : "f"(f1 - g1), "f"(f0 - g0));
}
__device__ __forceinline__ void split1(float v, __nv_bfloat16& h, __nv_bfloat16& l) {
    h = __float2bfloat16(v);
    l = __float2bfloat16(v - __bfloat162float(h));
}

// ---------------- split kernel: f32 -> bf16 hi + bf16 lo --------------------
__global__ void split_kernel(const float* __restrict__ src,
                             __nv_bfloat16* __restrict__ hi,
                             __nv_bfloat16* __restrict__ lo, int n4) {
    int i = blockIdx.x * 256 + threadIdx.x;
    if (i >= n4) return;
    float4 v = ((const float4*)src)[i];
    __nv_bfloat16 h0, h1, h2, h3, l0, l1, l2, l3;
    split1(v.x, h0, l0); split1(v.y, h1, l1);
    split1(v.z, h2, l2); split1(v.w, h3, l3);
    ((__nv_bfloat162*)hi)[i * 2]     = __nv_bfloat162(h0, h1);
    ((__nv_bfloat162*)hi)[i * 2 + 1] = __nv_bfloat162(h2, h3);
    ((__nv_bfloat162*)lo)[i * 2]     = __nv_bfloat162(l0, l1);
    ((__nv_bfloat162*)lo)[i * 2 + 1] = __nv_bfloat162(l2, l3);
}

// ---------------- rel-bias gather -------------------------------------------
__global__ void relbias_kernel(const float* __restrict__ table,
                               const int* __restrict__ idx) {
    int i = blockIdx.x * 256 + threadIdx.x;
    if (i < NN_) {
        int id = idx[i];
        #pragma unroll
        for (int h = 0; h < H_; h++)
            g_relbias[h * NN_ + i] = table[id * H_ + h];
    }
}

// ---------------- bf16-split TN GEMM: D = A @ W^T ---------------------------
// A[M,768] hi/lo, W[Ntot,768] hi/lo. CTA tile 128x128, K chunk = 32 bf16.
// smem row stride 56 elems (112B): 16B-aligned, conflict-free frag reads.
#define KCH     24
#define GPLANE  14336                 // 128 * 56 * 2
#define GSTAGE  (4 * GPLANE)          // 57344
#define GSM_B   (2 * GSTAGE)          // 114688
#define GRW     28                    // words per smem row

template<int MODE>
__global__ void __launch_bounds__(256) gemm5(const __nv_bfloat16* __restrict__ Ah,
                                             const __nv_bfloat16* __restrict__ Al,
                                             const __nv_bfloat16* __restrict__ Wh,
                                             const __nv_bfloat16* __restrict__ Wl,
                                             const float* __restrict__ bias_q,
                                             const float* __restrict__ bias_v,
                                             float* __restrict__ outp) {
    extern __shared__ char smem[];
    const uint32_t sb = sm_u32(smem);
    const int tid = threadIdx.x, lane = tid & 31, warp = tid >> 5;
    const int g = lane >> 2, tg = lane & 3;
    const int wm = warp >> 1, wn = warp & 1;
    const int bn = blockIdx.x, bm = blockIdx.y;

    const __nv_bfloat16* p0 = Ah + (size_t)bm * 128 * 768;
    const __nv_bfloat16* p1 = Al + (size_t)bm * 128 * 768;
    const __nv_bfloat16* p2 = Wh + (size_t)bn * 128 * 768;
    const __nv_bfloat16* p3 = Wl + (size_t)bn * 128 * 768;

    float acc[2][8][4];
    #pragma unroll
    for (int i = 0; i < 2; i++)
        #pragma unroll
        for (int j = 0; j < 8; j++)
            #pragma unroll
            for (int l = 0; l < 4; l++) acc[i][j][l] = 0.f;

    auto load_chunk = [&](int kc, int st) {
        uint32_t dstb = sb + st * GSTAGE;
        #pragma unroll
        for (int i = 0; i < 8; i++) {
            int u = tid + i * 256;
            int t = u >> 9, w = u & 511;
            int row = w >> 2, c16 = w & 3;
            const __nv_bfloat16* src =
                (t == 0 ? p0 : t == 1 ? p1 : t == 2 ? p2 : p3)
                + (size_t)row * 768 + kc * 32 + c16 * 8;
            cp16(dstb + t * GPLANE + row * 112 + c16 * 16, src);
        }
        asm volatile("cp.async.commit_group;");
    };

    load_chunk(0, 0);
    load_chunk(1, 1);

    for (int kt = 0; kt < KCH; kt++) {
        if (kt == KCH - 1) asm volatile("cp.async.wait_group 0;");
        else               asm volatile("cp.async.wait_group 1;");
        __syncthreads();

        const int cur = kt & 1;
        const uint32_t* AH = (const uint32_t*)(smem + cur * GSTAGE);
        const uint32_t* AL = AH + GPLANE / 4;
        const uint32_t* BH = AH + 2 * (GPLANE / 4);
        const uint32_t* BL = AH + 3 * (GPLANE / 4);

        #pragma unroll
        for (int ks = 0; ks < 2; ks++) {
            const int kw = ks * 8 + tg;
            uint32_t ah[2][4], al[2][4];
            #pragma unroll
            for (int mt = 0; mt < 2; mt++) {
                int r = wm * 32 + mt * 16 + g;
                ah[mt][0] = AH[r * GRW + kw];       ah[mt][1] = AH[(r + 8) * GRW + kw];
                ah[mt][2] = AH[r * GRW + kw + 4];   ah[mt][3] = AH[(r + 8) * GRW + kw + 4];
                al[mt][0] = AL[r * GRW + kw];       al[mt][1] = AL[(r + 8) * GRW + kw];
                al[mt][2] = AL[r * GRW + kw + 4];   al[mt][3] = AL[(r + 8) * GRW + kw + 4];
            }
            #pragma unroll
            for (int nt = 0; nt < 8; nt++) {
                int nc = wn * 64 + nt * 8 + g;
                uint32_t bh0 = BH[nc * GRW + kw], bh1 = BH[nc * GRW + kw + 4];
                uint32_t bl0 = BL[nc * GRW + kw], bl1 = BL[nc * GRW + kw + 4];
                mma3(acc[0][nt], ah[0], al[0], bh0, bh1, bl0, bl1);
                mma3(acc[1][nt], ah[1], al[1], bh0, bh1, bl0, bl1);
            }
        }
        __syncthreads();
        if (kt + 2 < KCH) load_chunk(kt + 2, cur);
    }

    // ---------------- epilogue ----------------
    if (MODE == 0) {
        const int which = bn / 6;                    // 0=q 1=k 2=v
        const int h = (bn % 6) * 2 + wn;             // head (constant per warp)
        __nv_bfloat16* dh = (which == 0) ? g_qh : (which == 1) ? g_kh : g_vh;
        __nv_bfloat16* dl = (which == 0) ? g_ql : (which == 1) ? g_kl : g_vl;
        #pragma unroll
        for (int mt = 0; mt < 2; mt++)
            #pragma unroll
            for (int hf = 0; hf < 2; hf++) {
                int r = bm * 128 + wm * 32 + mt * 16 + g + hf * 8;
                int bb = r / N_, np = r - bb * N_;
                size_t rowoff = ((size_t)(bb * H_ + h) * N_ + np) * HD_;
                #pragma unroll
                for (int nt = 0; nt < 8; nt++) {
                    int d0 = nt * 8 + 2 * tg;
                    float a0 = 0.f, a1 = 0.f;
                    if (which == 0) { a0 = bias_q[h * 64 + d0]; a1 = bias_q[h * 64 + d0 + 1]; }
                    else if (which == 2) { a0 = bias_v[h * 64 + d0]; a1 = bias_v[h * 64 + d0 + 1]; }
                    float v0 = acc[mt][nt][hf * 2] + a0;
                    float v1 = acc[mt][nt][hf * 2 + 1] + a1;
                    if (which == 0) { v0 *= 0.125f; v1 *= 0.125f; }
                    __nv_bfloat16 h0, h1, l0, l1;
                    split1(v0, h0, l0); split1(v1, h1, l1);
                    *(__nv_bfloat162*)(dh + rowoff + d0) = __nv_bfloat162(h0, h1);
                    *(__nv_bfloat162*)(dl + rowoff + d0) = __nv_bfloat162(l0, l1);
                }
            }
    } else {
        #pragma unroll
        for (int mt = 0; mt < 2; mt++)
            #pragma unroll
            for (int hf = 0; hf < 2; hf++) {
                int r = bm * 128 + wm * 32 + mt * 16 + g + hf * 8;
                float* rowp = outp + (size_t)r * 768;
                #pragma unroll
                for (int nt = 0; nt < 8; nt++) {
                    int colg = bn * 128 + wn * 64 + nt * 8 + 2 * tg;
                    rowp[colg] = acc[mt][nt][hf * 2] + bias_q[colg];
                    rowp[colg + 1] = acc[mt][nt][hf * 2 + 1] + bias_q[colg + 1];
                }
            }
    }
}

// ---------------- fused attention per (row-chunk, head, batch) --------------
// smem bytes: QH[128x72 bf16]=18432 | QL=18432 | KH[208x72]=29952 | KL=29952 |
//             S fp32 [128][212] = 108544.  vT planes overlay K region.
#define AQH 0
#define AQL 18432
#define AKH 36864
#define AKL 66816
#define AS  96768
#define ATT_SMEM (AS + 128 * 212 * 4)   // 205312
#define AVH 36864
#define AVL 64512
#define QKW 36      // words per q/k smem row (72 bf16)
#define VTW 108     // words per vT smem row (216 bf16)

__global__ void __launch_bounds__(256) attn_kernel() {
    extern __shared__ char smem[];
    const int tid = threadIdx.x, lane = tid & 31, warp = tid >> 5;
    const int g = lane >> 2, tg = lane & 3;
    const int wm = warp >> 1, wn = warp & 1;
    const int r0 = blockIdx.x * 128;
    const int h = blockIdx.y, b = blockIdx.z;

    const size_t hoff = (size_t)(b * H_ + h) * N_ * HD_;
    const __nv_bfloat16* qh = g_qh + hoff;
    const __nv_bfloat16* ql = g_ql + hoff;
    const __nv_bfloat16* kh = g_kh + hoff;
    const __nv_bfloat16* kl = g_kl + hoff;
    const __nv_bfloat16* vh = g_vh + hoff;
    const __nv_bfloat16* vl = g_vl + hoff;
    float* S = (float*)(smem + AS);

    // load q (128 rows) and k (208 rows) hi/lo planes, zero-padded
    for (int e = tid; e < 128 * 8; e += 256) {
        int row = e >> 3, c = e & 7;
        int gr = r0 + row;
        float4 zh = make_float4(0, 0, 0, 0), zl = zh;
        if (gr < N_) {
            zh = *(const float4*)(qh + (size_t)gr * HD_ + c * 8);
            zl = *(const float4*)(ql + (size_t)gr * HD_ + c * 8);
        }
        *(float4*)(smem + AQH + row * 144 + c * 16) = zh;
        *(float4*)(smem + AQL + row * 144 + c * 16) = zl;
    }
    for (int e = tid; e < 208 * 8; e += 256) {
        int row = e >> 3, c = e & 7;
        float4 zh = make_float4(0, 0, 0, 0), zl = zh;
        if (row < N_) {
            zh = *(const float4*)(kh + (size_t)row * HD_ + c * 8);
            zl = *(const float4*)(kl + (size_t)row * HD_ + c * 8);
        }
        *(float4*)(smem + AKH + row * 144 + c * 16) = zh;
        *(float4*)(smem + AKL + row * 144 + c * 16) = zl;
    }
    __syncthreads();

    // ---- S = q . k^T  (warp tile 32 x 104, 13 n-tiles, K=64 -> 4 ksteps) ----
    float cc[2][13][4];
    #pragma unroll
    for (int i = 0; i < 2; i++)
        #pragma unroll
        for (int j = 0; j < 13; j++)
            #pragma unroll
            for (int l = 0; l < 4; l++) cc[i][j][l] = 0.f;
    {
        const uint32_t* QH = (const uint32_t*)(smem + AQH);
        const uint32_t* QL = (const uint32_t*)(smem + AQL);
        const uint32_t* KH = (const uint32_t*)(smem + AKH);
        const uint32_t* KL = (const uint32_t*)(smem + AKL);
        #pragma unroll
        for (int ks = 0; ks < 4; ks++) {
            const int kw = ks * 8 + tg;
            uint32_t ah[2][4], al[2][4];
            #pragma unroll
            for (int mt = 0; mt < 2; mt++) {
                int r = wm * 32 + mt * 16 + g;
                ah[mt][0] = QH[r * QKW + kw];     ah[mt][1] = QH[(r + 8) * QKW + kw];
                ah[mt][2] = QH[r * QKW + kw + 4]; ah[mt][3] = QH[(r + 8) * QKW + kw + 4];
                al[mt][0] = QL[r * QKW + kw];     al[mt][1] = QL[(r + 8) * QKW + kw];
                al[mt][2] = QL[r * QKW + kw + 4]; al[mt][3] = QL[(r + 8) * QKW + kw + 4];
            }
            #pragma unroll
            for (int nt = 0; nt < 13; nt++) {
                int nc = wn * 104 + nt * 8 + g;
                uint32_t bh0 = KH[nc * QKW + kw], bh1 = KH[nc * QKW + kw + 4];
                uint32_t bl0 = KL[nc * QKW + kw], bl1 = KL[nc * QKW + kw + 4];
                mma3(cc[0][nt], ah[0], al[0], bh0, bh1, bl0, bl1);
                mma3(cc[1][nt], ah[1], al[1], bh0, bh1, bl0, bl1);
            }
        }
    }

    // write S (+rel bias); pad cols [N_,208) to 0
    #pragma unroll
    for (int mt = 0; mt < 2; mt++)
        #pragma unroll
        for (int hf = 0; hf < 2; hf++) {
            int rl = wm * 32 + mt * 16 + g + hf * 8;
            int ig = r0 + rl;
            const float* rb = g_relbias + (size_t)h * NN_ + (size_t)min(ig, N_ - 1) * N_;
            #pragma unroll
            for (int nt = 0; nt < 13; nt++) {
                int j0 = wn * 104 + nt * 8 + 2 * tg;
                float v0 = (j0 < N_)     ? cc[mt][nt][hf * 2]     + rb[j0]     : 0.f;
                float v1 = (j0 + 1 < N_) ? cc[mt][nt][hf * 2 + 1] + rb[j0 + 1] : 0.f;
                S[rl * 212 + j0] = v0;
                S[rl * 212 + j0 + 1] = v1;
            }
        }
    __syncthreads();   // k planes dead -> reuse as vT planes

    // vT hi/lo: [d][j] bf16, stride 216; zero-pad cols [197,208)
    for (int e = tid; e < N_ * 8; e += 256) {
        int j = e >> 3, d8 = (e & 7) * 8;
        float4 vh4 = *(const float4*)(vh + (size_t)j * HD_ + d8);
        float4 vl4 = *(const float4*)(vl + (size_t)j * HD_ + d8);
        const __nv_bfloat16* ph = (const __nv_bfloat16*)&vh4;
        const __nv_bfloat16* pl = (const __nv_bfloat16*)&vl4;
        #pragma unroll
        for (int i = 0; i < 8; i++) {
            *(__nv_bfloat16*)(smem + AVH + (d8 + i) * 432 + j * 2) = ph[i];
            *(__nv_bfloat16*)(smem + AVL + (d8 + i) * 432 + j * 2) = pl[i];
        }
    }
    for (int e = tid; e < 64 * 11; e += 256) {
        int d = e / 11, j = N_ + (e % 11);
        *(__nv_bfloat16*)(smem + AVH + d * 432 + j * 2) = __float2bfloat16(0.f);
        *(__nv_bfloat16*)(smem + AVL + d * 432 + j * 2) = __float2bfloat16(0.f);
    }

    // softmax: 16 rows per warp
    for (int rr = 0; rr < 16; rr++) {
        int row = warp * 16 + rr;
        float* Sr = S + row * 212;
        float mx = -1e30f;
        for (int j = lane; j < N_; j += 32) mx = fmaxf(mx, Sr[j]);
        #pragma unroll
        for (int o = 16; o; o >>= 1) mx = fmaxf(mx, __shfl_xor_sync(0xffffffffu, mx, o));
        float sum = 0.f;
        for (int j = lane; j < N_; j += 32) {
            float e = __expf(Sr[j] - mx);
            Sr[j] = e; sum += e;
        }
        #pragma unroll
        for (int o = 16; o; o >>= 1) sum += __shfl_xor_sync(0xffffffffu, sum, o);
        float inv = 1.f / sum;
        for (int j = lane; j < N_; j += 32) Sr[j] *= inv;
        for (int j = N_ + lane; j < 208; j += 32) Sr[j] = 0.f;
    }
    __syncthreads();

    // ---- O = S . v  (warp tile 32 x 32, 13 ksteps of 16) ----
    float oo[2][4][4];
    #pragma unroll
    for (int i = 0; i < 2; i++)
        #pragma unroll
        for (int j = 0; j < 4; j++)
            #pragma unroll
            for (int l = 0; l < 4; l++) oo[i][j][l] = 0.f;
    {
        const uint32_t* VH = (const uint32_t*)(smem + AVH);
        const uint32_t* VL = (const uint32_t*)(smem + AVL);
        #pragma unroll 2
        for (int ks = 0; ks < 13; ks++) {
            const int k0 = ks * 16;
            uint32_t ah[2][4], al[2][4];
            #pragma unroll
            for (int mt = 0; mt < 2; mt++) {
                int r = wm * 32 + mt * 16 + g;
                float2 f;
                f = *(const float2*)(S + r * 212 + k0 + 2 * tg);
                pack_split2(f.x, f.y, ah[mt][0], al[mt][0]);
                f = *(const float2*)(S + (r + 8) * 212 + k0 + 2 * tg);
                pack_split2(f.x, f.y, ah[mt][1], al[mt][1]);
                f = *(const float2*)(S + r * 212 + k0 + 8 + 2 * tg);
                pack_split2(f.x, f.y, ah[mt][2], al[mt][2]);
                f = *(const float2*)(S + (r + 8) * 212 + k0 + 8 + 2 * tg);
                pack_split2(f.x, f.y, ah[mt][3], al[mt][3]);
            }
            const int kw = ks * 8 + tg;
            #pragma unroll
            for (int nt = 0; nt < 4; nt++) {
                int nc = wn * 32 + nt * 8 + g;
                uint32_t bh0 = VH[nc * VTW + kw], bh1 = VH[nc * VTW + kw + 4];
                uint32_t bl0 = VL[nc * VTW + kw], bl1 = VL[nc * VTW + kw + 4];
                mma3(oo[0][nt], ah[0], al[0], bh0, bh1, bl0, bl1);
                mma3(oo[1][nt], ah[1], al[1], bh0, bh1, bl0, bl1);
            }
        }
    }

    // write attention output as bf16 hi/lo split for the proj GEMM
    #pragma unroll
    for (int mt = 0; mt < 2; mt++)
        #pragma unroll
        for (int hf = 0; hf < 2; hf++) {
            int rl = wm * 32 + mt * 16 + g + hf * 8;
            int ig = r0 + rl;
            if (ig < N_) {
                size_t base = ((size_t)b * N_ + ig) * C_ + h * HD_;
                #pragma unroll
                for (int nt = 0; nt < 4; nt++) {
                    int d0 = wn * 32 + nt * 8 + 2 * tg;
                    float v0 = oo[mt][nt][hf * 2];
                    float v1 = oo[mt][nt][hf * 2 + 1];
                    __nv_bfloat16 h0, h1, l0, l1;
                    split1(v0, h0, l0); split1(v1, h1, l1);
                    *(__nv_bfloat162*)(g_att_hi + base + d0) = __nv_bfloat162(h0, h1);
                    *(__nv_bfloat162*)(g_att_lo + base + d0) = __nv_bfloat162(l0, l1);
                }
            }
        }
}

// ---------------- launch ----------------------------------------------------
extern "C" void kernel_launch(void* const* d_in, const int* in_sizes, int n_in,
                              void* d_out, int out_size) {
    const float* x       = (const float*)d_in[0];
    const float* qkv_w   = (const float*)d_in[1];
    const float* q_bias  = (const float*)d_in[2];
    const float* v_bias  = (const float*)d_in[3];
    const float* table   = (const float*)d_in[4];
    const float* proj_w  = (const float*)d_in[5];
    const float* proj_b  = (const float*)d_in[6];
    const int*   rel_idx = (const int*)d_in[7];
    float* out = (float*)d_out;

    cudaFuncSetAttribute(gemm5<0>, cudaFuncAttributeMaxDynamicSharedMemorySize, GSM_B);
    cudaFuncSetAttribute(gemm5<1>, cudaFuncAttributeMaxDynamicSharedMemorySize, GSM_B);
    cudaFuncSetAttribute(attn_kernel, cudaFuncAttributeMaxDynamicSharedMemorySize, ATT_SMEM);

    __nv_bfloat16 *xh, *xl, *wqh, *wql, *wph, *wpl, *ath, *atl;
    cudaGetSymbolAddress((void**)&xh,  g_x_hi);
    cudaGetSymbolAddress((void**)&xl,  g_x_lo);
    cudaGetSymbolAddress((void**)&wqh, g_wqkv_hi);
    cudaGetSymbolAddress((void**)&wql, g_wqkv_lo);
    cudaGetSymbolAddress((void**)&wph, g_wp_hi);
    cudaGetSymbolAddress((void**)&wpl, g_wp_lo);
    cudaGetSymbolAddress((void**)&ath, g_att_hi);
    cudaGetSymbolAddress((void**)&atl, g_att_lo);

    split_kernel<<<(M_*C_/4 + 255)/256, 256>>>(x, xh, xl, M_*C_/4);
    split_kernel<<<(3*C_*C_/4 + 255)/256, 256>>>(qkv_w, wqh, wql, 3*C_*C_/4);
    split_kernel<<<(C_*C_/4 + 255)/256, 256>>>(proj_w, wph, wpl, C_*C_/4);
    relbias_kernel<<<(NN_ + 255)/256, 256>>>(table, rel_idx);

    gemm5<0><<<dim3(18, 197), 256, GSM_B>>>(xh, xl, wqh, wql, q_bias, v_bias, nullptr);

    attn_kernel<<<dim3(2, H_, B_), 256, ATT_SMEM>>>();

    gemm5<1><<<dim3(6, 197), 256, GSM_B>>>(ath, atl, wph, wpl, proj_b, nullptr, out);
}

// round 8
// speedup vs baseline: 1.8336x; 1.1436x over previous
#include <cuda_runtime.h>
#include <cuda_bf16.h>
#include <cstdint>

#define B_   128
#define N_   197
#define C_   768
#define H_   12
#define HD_  64
#define M_   (B_*N_)      // 25216
#define NN_  (N_*N_)      // 38809
#define PL_  (B_*H_*N_*HD_)

// ---------------- scratch (device globals; no allocation allowed) -----------
__device__ float g_relbias[H_*NN_];                       // [H,N,N]
__device__ __nv_bfloat16 g_qh[PL_], g_ql[PL_];            // q split [B,H,N,64]
__device__ __nv_bfloat16 g_kh[PL_], g_kl[PL_];
__device__ __nv_bfloat16 g_vh[PL_], g_vl[PL_];
__device__ __nv_bfloat16 g_x_hi[M_*C_],  g_x_lo[M_*C_];
__device__ __nv_bfloat16 g_att_hi[M_*C_], g_att_lo[M_*C_];
__device__ __nv_bfloat16 g_wqkv_hi[3*C_*C_], g_wqkv_lo[3*C_*C_];
__device__ __nv_bfloat16 g_wp_hi[C_*C_],  g_wp_lo[C_*C_];

// ---------------- helpers ---------------------------------------------------
__device__ __forceinline__ void cp16(uint32_t smem_dst, const void* gsrc) {
    asm volatile("cp.async.cg.shared.global [%0], [%1], 16;" :: "r"(smem_dst), "l"(gsrc));
}
__device__ __forceinline__ uint32_t sm_u32(const void* p) {
    uint32_t a;
    asm("{ .reg .u64 t; cvta.to.shared.u64 t, %1; cvt.u32.u64 %0, t; }" : "=r"(a) : "l"(p));
    return a;
}
__device__ __forceinline__ void mma_bf16(float c[4], const uint32_t a[4],
                                         uint32_t b0, uint32_t b1) {
    asm volatile(
        "mma.sync.aligned.m16n8k16.row.col.f32.bf16.bf16.f32 "
        "{%0,%1,%2,%3}, {%4,%5,%6,%7}, {%8,%9}, {%0,%1,%2,%3};\n"
        : "+f"(c[0]), "+f"(c[1]), "+f"(c[2]), "+f"(c[3])
        : "r"(a[0]), "r"(a[1]), "r"(a[2]), "r"(a[3]), "r"(b0), "r"(b1));
}
__device__ __forceinline__ void mma3(float c[4], const uint32_t ah[4],
                                     const uint32_t al[4],
                                     uint32_t bh0, uint32_t bh1,
                                     uint32_t bl0, uint32_t bl1) {
    mma_bf16(c, ah, bh0, bh1);
    mma_bf16(c, al, bh0, bh1);
    mma_bf16(c, ah, bl0, bl1);
}
// split two fp32 into packed bf16x2 hi + bf16x2 lo (f0 -> low half)
__device__ __forceinline__ void pack_split2(float f0, float f1,
                                            uint32_t& h, uint32_t& l) {
    asm("cvt.rn.bf16x2.f32 %0, %1, %2;" : "=r"(h) : "f"(f1), "f"(f0));
    float g1 = __uint_as_float(h & 0xffff0000u);
    float g0 = __uint_as_float(h << 16);
    asm("cvt.rn.bf16x2.f32 %0, %1, %2;" : "=r"(l) : "f"(f1 - g1), "f"(f0 - g0));
}
__device__ __forceinline__ void split1(float v, __nv_bfloat16& h, __nv_bfloat16& l) {
    h = __float2bfloat16(v);
    l = __float2bfloat16(v - __bfloat162float(h));
}

// ---------------- split kernel: f32 -> bf16 hi + bf16 lo --------------------
__global__ void split_kernel(const float* __restrict__ src,
                             __nv_bfloat16* __restrict__ hi,
                             __nv_bfloat16* __restrict__ lo, int n4) {
    int i = blockIdx.x * 256 + threadIdx.x;
    if (i >= n4) return;
    float4 v = ((const float4*)src)[i];
    __nv_bfloat16 h0, h1, h2, h3, l0, l1, l2, l3;
    split1(v.x, h0, l0); split1(v.y, h1, l1);
    split1(v.z, h2, l2); split1(v.w, h3, l3);
    ((__nv_bfloat162*)hi)[i * 2]     = __nv_bfloat162(h0, h1);
    ((__nv_bfloat162*)hi)[i * 2 + 1] = __nv_bfloat162(h2, h3);
    ((__nv_bfloat162*)lo)[i * 2]     = __nv_bfloat162(l0, l1);
    ((__nv_bfloat162*)lo)[i * 2 + 1] = __nv_bfloat162(l2, l3);
}

// ---------------- rel-bias gather -------------------------------------------
__global__ void relbias_kernel(const float* __restrict__ table,
                               const int* __restrict__ idx) {
    int i = blockIdx.x * 256 + threadIdx.x;
    if (i < NN_) {
        int id = idx[i];
        #pragma unroll
        for (int h = 0; h < H_; h++)
            g_relbias[h * NN_ + i] = table[id * H_ + h];
    }
}

// ---------------- bf16-split TN GEMM: D = A @ W^T (3-stage pipeline) --------
#define KCH     24
#define GPLANE  14336                 // 128 * 56 * 2
#define GSTAGE  (4 * GPLANE)          // 57344
#define GSM_B   (3 * GSTAGE)          // 172032
#define GRW     28                    // words per smem row

template<int MODE>
__global__ void __launch_bounds__(256) gemm5(const __nv_bfloat16* __restrict__ Ah,
                                             const __nv_bfloat16* __restrict__ Al,
                                             const __nv_bfloat16* __restrict__ Wh,
                                             const __nv_bfloat16* __restrict__ Wl,
                                             const float* __restrict__ bias_q,
                                             const float* __restrict__ bias_v,
                                             float* __restrict__ outp) {
    extern __shared__ char smem[];
    const uint32_t sb = sm_u32(smem);
    const int tid = threadIdx.x, lane = tid & 31, warp = tid >> 5;
    const int g = lane >> 2, tg = lane & 3;
    const int wm = warp >> 1, wn = warp & 1;
    const int bn = blockIdx.x, bm = blockIdx.y;

    const __nv_bfloat16* p0 = Ah + (size_t)bm * 128 * 768;
    const __nv_bfloat16* p1 = Al + (size_t)bm * 128 * 768;
    const __nv_bfloat16* p2 = Wh + (size_t)bn * 128 * 768;
    const __nv_bfloat16* p3 = Wl + (size_t)bn * 128 * 768;

    float acc[2][8][4];
    #pragma unroll
    for (int i = 0; i < 2; i++)
        #pragma unroll
        for (int j = 0; j < 8; j++)
            #pragma unroll
            for (int l = 0; l < 4; l++) acc[i][j][l] = 0.f;

    auto load_chunk = [&](int kc, int st) {
        uint32_t dstb = sb + st * GSTAGE;
        #pragma unroll
        for (int i = 0; i < 8; i++) {
            int u = tid + i * 256;
            int t = u >> 9, w = u & 511;
            int row = w >> 2, c16 = w & 3;
            const __nv_bfloat16* src =
                (t == 0 ? p0 : t == 1 ? p1 : t == 2 ? p2 : p3)
                + (size_t)row * 768 + kc * 32 + c16 * 8;
            cp16(dstb + t * GPLANE + row * 112 + c16 * 16, src);
        }
        asm volatile("cp.async.commit_group;");
    };

    load_chunk(0, 0);
    load_chunk(1, 1);

    for (int kt = 0; kt < KCH; kt++) {
        if (kt == KCH - 1) asm volatile("cp.async.wait_group 0;");
        else               asm volatile("cp.async.wait_group 1;");
        __syncthreads();

        const int cur = kt % 3;
        const uint32_t* AH = (const uint32_t*)(smem + cur * GSTAGE);
        const uint32_t* AL = AH + GPLANE / 4;
        const uint32_t* BH = AH + 2 * (GPLANE / 4);
        const uint32_t* BL = AH + 3 * (GPLANE / 4);

        #pragma unroll
        for (int ks = 0; ks < 2; ks++) {
            const int kw = ks * 8 + tg;
            uint32_t ah[2][4], al[2][4];
            #pragma unroll
            for (int mt = 0; mt < 2; mt++) {
                int r = wm * 32 + mt * 16 + g;
                ah[mt][0] = AH[r * GRW + kw];       ah[mt][1] = AH[(r + 8) * GRW + kw];
                ah[mt][2] = AH[r * GRW + kw + 4];   ah[mt][3] = AH[(r + 8) * GRW + kw + 4];
                al[mt][0] = AL[r * GRW + kw];       al[mt][1] = AL[(r + 8) * GRW + kw];
                al[mt][2] = AL[r * GRW + kw + 4];   al[mt][3] = AL[(r + 8) * GRW + kw + 4];
            }
            #pragma unroll
            for (int nt = 0; nt < 8; nt++) {
                int nc = wn * 64 + nt * 8 + g;
                uint32_t bh0 = BH[nc * GRW + kw], bh1 = BH[nc * GRW + kw + 4];
                uint32_t bl0 = BL[nc * GRW + kw], bl1 = BL[nc * GRW + kw + 4];
                mma3(acc[0][nt], ah[0], al[0], bh0, bh1, bl0, bl1);
                mma3(acc[1][nt], ah[1], al[1], bh0, bh1, bl0, bl1);
            }
        }
        if (kt + 2 < KCH) load_chunk(kt + 2, (kt + 2) % 3);
    }

    // ---------------- epilogue ----------------
    if (MODE == 0) {
        const int which = bn / 6;                    // 0=q 1=k 2=v
        const int h = (bn % 6) * 2 + wn;
        __nv_bfloat16* dh = (which == 0) ? g_qh : (which == 1) ? g_kh : g_vh;
        __nv_bfloat16* dl = (which == 0) ? g_ql : (which == 1) ? g_kl : g_vl;
        #pragma unroll
        for (int mt = 0; mt < 2; mt++)
            #pragma unroll
            for (int hf = 0; hf < 2; hf++) {
                int r = bm * 128 + wm * 32 + mt * 16 + g + hf * 8;
                int bb = r / N_, np = r - bb * N_;
                size_t rowoff = ((size_t)(bb * H_ + h) * N_ + np) * HD_;
                #pragma unroll
                for (int nt = 0; nt < 8; nt++) {
                    int d0 = nt * 8 + 2 * tg;
                    float a0 = 0.f, a1 = 0.f;
                    if (which == 0) { a0 = bias_q[h * 64 + d0]; a1 = bias_q[h * 64 + d0 + 1]; }
                    else if (which == 2) { a0 = bias_v[h * 64 + d0]; a1 = bias_v[h * 64 + d0 + 1]; }
                    float v0 = acc[mt][nt][hf * 2] + a0;
                    float v1 = acc[mt][nt][hf * 2 + 1] + a1;
                    if (which == 0) { v0 *= 0.125f; v1 *= 0.125f; }
                    __nv_bfloat16 h0, h1, l0, l1;
                    split1(v0, h0, l0); split1(v1, h1, l1);
                    *(__nv_bfloat162*)(dh + rowoff + d0) = __nv_bfloat162(h0, h1);
                    *(__nv_bfloat162*)(dl + rowoff + d0) = __nv_bfloat162(l0, l1);
                }
            }
    } else {
        #pragma unroll
        for (int mt = 0; mt < 2; mt++)
            #pragma unroll
            for (int hf = 0; hf < 2; hf++) {
                int r = bm * 128 + wm * 32 + mt * 16 + g + hf * 8;
                float* rowp = outp + (size_t)r * 768;
                #pragma unroll
                for (int nt = 0; nt < 8; nt++) {
                    int colg = bn * 128 + wn * 64 + nt * 8 + 2 * tg;
                    rowp[colg] = acc[mt][nt][hf * 2] + bias_q[colg];
                    rowp[colg + 1] = acc[mt][nt][hf * 2 + 1] + bias_q[colg + 1];
                }
            }
    }
}

// ---------------- flash attention: register softmax, 64 rows/CTA ------------
// smem: QH[64][72 bf16] | QL | KH[208][72] | KL.  vT planes overlay K region.
#define AT_QH 0
#define AT_QL 9216
#define AT_KH 18432
#define AT_KL 48384
#define AT_SM 78336
#define AT_VH 18432          // vT hi: [64][218 bf16] stride 436B
#define AT_VL 46336
#define QKW 36               // words per q/k smem row (72 bf16)
#define VTW 109              // words per vT smem row (218 bf16)

__global__ void __launch_bounds__(128) attn_kernel() {
    extern __shared__ char smem[];
    const int tid = threadIdx.x, lane = tid & 31, warp = tid >> 5;
    const int g = lane >> 2, tg = lane & 3;
    const int r0 = blockIdx.x * 64;
    const int h = blockIdx.y, b = blockIdx.z;

    const size_t hoff = (size_t)(b * H_ + h) * N_ * HD_;
    const __nv_bfloat16* qhp = g_qh + hoff;
    const __nv_bfloat16* qlp = g_ql + hoff;
    const __nv_bfloat16* khp = g_kh + hoff;
    const __nv_bfloat16* klp = g_kl + hoff;
    const __nv_bfloat16* vhp = g_vh + hoff;
    const __nv_bfloat16* vlp = g_vl + hoff;

    // load q (64 rows) and k (208 rows) hi/lo planes, zero-padded
    for (int e = tid; e < 64 * 8; e += 128) {
        int row = e >> 3, c = e & 7;
        int gr = r0 + row;
        float4 zh = make_float4(0, 0, 0, 0), zl = zh;
        if (gr < N_) {
            zh = *(const float4*)(qhp + (size_t)gr * HD_ + c * 8);
            zl = *(const float4*)(qlp + (size_t)gr * HD_ + c * 8);
        }
        *(float4*)(smem + AT_QH + row * 144 + c * 16) = zh;
        *(float4*)(smem + AT_QL + row * 144 + c * 16) = zl;
    }
    for (int e = tid; e < 208 * 8; e += 128) {
        int row = e >> 3, c = e & 7;
        float4 zh = make_float4(0, 0, 0, 0), zl = zh;
        if (row < N_) {
            zh = *(const float4*)(khp + (size_t)row * HD_ + c * 8);
            zl = *(const float4*)(klp + (size_t)row * HD_ + c * 8);
        }
        *(float4*)(smem + AT_KH + row * 144 + c * 16) = zh;
        *(float4*)(smem + AT_KL + row * 144 + c * 16) = zl;
    }
    __syncthreads();

    // ---- S = q . k^T : warp owns 16 rows x 208 cols, cc in registers ----
    float cc[26][4];
    #pragma unroll
    for (int j = 0; j < 26; j++)
        #pragma unroll
        for (int l = 0; l < 4; l++) cc[j][l] = 0.f;
    {
        const uint32_t* QH = (const uint32_t*)(smem + AT_QH);
        const uint32_t* QL = (const uint32_t*)(smem + AT_QL);
        const uint32_t* KH = (const uint32_t*)(smem + AT_KH);
        const uint32_t* KL = (const uint32_t*)(smem + AT_KL);
        #pragma unroll
        for (int ks = 0; ks < 4; ks++) {
            const int kw = ks * 8 + tg;
            const int r = warp * 16 + g;
            uint32_t ah[4], al[4];
            ah[0] = QH[r * QKW + kw];     ah[1] = QH[(r + 8) * QKW + kw];
            ah[2] = QH[r * QKW + kw + 4]; ah[3] = QH[(r + 8) * QKW + kw + 4];
            al[0] = QL[r * QKW + kw];     al[1] = QL[(r + 8) * QKW + kw];
            al[2] = QL[r * QKW + kw + 4]; al[3] = QL[(r + 8) * QKW + kw + 4];
            #pragma unroll
            for (int nt = 0; nt < 26; nt++) {
                int nc = nt * 8 + g;
                uint32_t bh0 = KH[nc * QKW + kw], bh1 = KH[nc * QKW + kw + 4];
                uint32_t bl0 = KL[nc * QKW + kw], bl1 = KL[nc * QKW + kw + 4];
                mma3(cc[nt], ah, al, bh0, bh1, bl0, bl1);
            }
        }
    }
    __syncthreads();   // K planes dead -> reuse as vT

    // vT hi/lo: [d][j] bf16, stride 218 elems; zero-pad cols [197,208)
    for (int e = tid; e < N_ * 8; e += 128) {
        int j = e >> 3, d8 = (e & 7) * 8;
        float4 vh4 = *(const float4*)(vhp + (size_t)j * HD_ + d8);
        float4 vl4 = *(const float4*)(vlp + (size_t)j * HD_ + d8);
        const __nv_bfloat16* ph = (const __nv_bfloat16*)&vh4;
        const __nv_bfloat16* pl = (const __nv_bfloat16*)&vl4;
        #pragma unroll
        for (int i = 0; i < 8; i++) {
            *(__nv_bfloat16*)(smem + AT_VH + (d8 + i) * 436 + j * 2) = ph[i];
            *(__nv_bfloat16*)(smem + AT_VL + (d8 + i) * 436 + j * 2) = pl[i];
        }
    }
    for (int e = tid; e < 64 * 11; e += 128) {
        int d = e / 11, j = N_ + (e % 11);
        *(__nv_bfloat16*)(smem + AT_VH + d * 436 + j * 2) = __float2bfloat16(0.f);
        *(__nv_bfloat16*)(smem + AT_VL + d * 436 + j * 2) = __float2bfloat16(0.f);
    }

    // ---- + rel bias, mask, register softmax (scalar loads: row stride 197
    //      floats is odd, so float2 loads would be misaligned) ----
    const int ig0 = r0 + warp * 16 + g, ig1 = ig0 + 8;
    {
        const float* rb0 = g_relbias + (size_t)h * NN_ + (size_t)min(ig0, N_ - 1) * N_;
        const float* rb1 = g_relbias + (size_t)h * NN_ + (size_t)min(ig1, N_ - 1) * N_;
        #pragma unroll
        for (int nt = 0; nt < 26; nt++) {
            int j0 = nt * 8 + 2 * tg;
            cc[nt][0] = (j0 < N_)     ? cc[nt][0] + rb0[j0]     : -1e30f;
            cc[nt][1] = (j0 + 1 < N_) ? cc[nt][1] + rb0[j0 + 1] : -1e30f;
            cc[nt][2] = (j0 < N_)     ? cc[nt][2] + rb1[j0]     : -1e30f;
            cc[nt][3] = (j0 + 1 < N_) ? cc[nt][3] + rb1[j0 + 1] : -1e30f;
        }
    }
    float mx0 = -1e30f, mx1 = -1e30f;
    #pragma unroll
    for (int nt = 0; nt < 26; nt++) {
        mx0 = fmaxf(mx0, fmaxf(cc[nt][0], cc[nt][1]));
        mx1 = fmaxf(mx1, fmaxf(cc[nt][2], cc[nt][3]));
    }
    mx0 = fmaxf(mx0, __shfl_xor_sync(0xffffffffu, mx0, 1));
    mx0 = fmaxf(mx0, __shfl_xor_sync(0xffffffffu, mx0, 2));
    mx1 = fmaxf(mx1, __shfl_xor_sync(0xffffffffu, mx1, 1));
    mx1 = fmaxf(mx1, __shfl_xor_sync(0xffffffffu, mx1, 2));
    float s0 = 0.f, s1 = 0.f;
    #pragma unroll
    for (int nt = 0; nt < 26; nt++) {
        cc[nt][0] = __expf(cc[nt][0] - mx0); s0 += cc[nt][0];
        cc[nt][1] = __expf(cc[nt][1] - mx0); s0 += cc[nt][1];
        cc[nt][2] = __expf(cc[nt][2] - mx1); s1 += cc[nt][2];
        cc[nt][3] = __expf(cc[nt][3] - mx1); s1 += cc[nt][3];
    }
    s0 += __shfl_xor_sync(0xffffffffu, s0, 1);
    s0 += __shfl_xor_sync(0xffffffffu, s0, 2);
    s1 += __shfl_xor_sync(0xffffffffu, s1, 1);
    s1 += __shfl_xor_sync(0xffffffffu, s1, 2);
    const float inv0 = 1.f / s0, inv1 = 1.f / s1;
    #pragma unroll
    for (int nt = 0; nt < 26; nt++) {
        cc[nt][0] *= inv0; cc[nt][1] *= inv0;
        cc[nt][2] *= inv1; cc[nt][3] *= inv1;
    }
    __syncthreads();   // vT ready

    // ---- O = P . v : A-fragments straight from cc registers ----
    float oo[8][4];
    #pragma unroll
    for (int j = 0; j < 8; j++)
        #pragma unroll
        for (int l = 0; l < 4; l++) oo[j][l] = 0.f;
    {
        const uint32_t* VH = (const uint32_t*)(smem + AT_VH);
        const uint32_t* VL = (const uint32_t*)(smem + AT_VL);
        #pragma unroll
        for (int t = 0; t < 13; t++) {
            uint32_t ah[4], al[4];
            pack_split2(cc[2 * t][0],     cc[2 * t][1],     ah[0], al[0]);
            pack_split2(cc[2 * t][2],     cc[2 * t][3],     ah[1], al[1]);
            pack_split2(cc[2 * t + 1][0], cc[2 * t + 1][1], ah[2], al[2]);
            pack_split2(cc[2 * t + 1][2], cc[2 * t + 1][3], ah[3], al[3]);
            const int kw = t * 8 + tg;
            #pragma unroll
            for (int nt = 0; nt < 8; nt++) {
                int nc = nt * 8 + g;
                uint32_t bh0 = VH[nc * VTW + kw], bh1 = VH[nc * VTW + kw + 4];
                uint32_t bl0 = VL[nc * VTW + kw], bl1 = VL[nc * VTW + kw + 4];
                mma3(oo[nt], ah, al, bh0, bh1, bl0, bl1);
            }
        }
    }

    // write attention output as bf16 hi/lo split for the proj GEMM
    if (ig0 < N_) {
        size_t base = ((size_t)b * N_ + ig0) * C_ + h * HD_;
        #pragma unroll
        for (int nt = 0; nt < 8; nt++) {
            int d0 = nt * 8 + 2 * tg;
            __nv_bfloat16 h0, h1, l0, l1;
            split1(oo[nt][0], h0, l0); split1(oo[nt][1], h1, l1);
            *(__nv_bfloat162*)(g_att_hi + base + d0) = __nv_bfloat162(h0, h1);
            *(__nv_bfloat162*)(g_att_lo + base + d0) = __nv_bfloat162(l0, l1);
        }
    }
    if (ig1 < N_) {
        size_t base = ((size_t)b * N_ + ig1) * C_ + h * HD_;
        #pragma unroll
        for (int nt = 0; nt < 8; nt++) {
            int d0 = nt * 8 + 2 * tg;
            __nv_bfloat16 h0, h1, l0, l1;
            split1(oo[nt][2], h0, l0); split1(oo[nt][3], h1, l1);
            *(__nv_bfloat162*)(g_att_hi + base + d0) = __nv_bfloat162(h0, h1);
            *(__nv_bfloat162*)(g_att_lo + base + d0) = __nv_bfloat162(l0, l1);
        }
    }
}

// ---------------- launch ----------------------------------------------------
extern "C" void kernel_launch(void* const* d_in, const int* in_sizes, int n_in,
                              void* d_out, int out_size) {
    const float* x       = (const float*)d_in[0];
    const float* qkv_w   = (const float*)d_in[1];
    const float* q_bias  = (const float*)d_in[2];
    const float* v_bias  = (const float*)d_in[3];
    const float* table   = (const float*)d_in[4];
    const float* proj_w  = (const float*)d_in[5];
    const float* proj_b  = (const float*)d_in[6];
    const int*   rel_idx = (const int*)d_in[7];
    float* out = (float*)d_out;

    cudaFuncSetAttribute(gemm5<0>, cudaFuncAttributeMaxDynamicSharedMemorySize, GSM_B);
    cudaFuncSetAttribute(gemm5<1>, cudaFuncAttributeMaxDynamicSharedMemorySize, GSM_B);
    cudaFuncSetAttribute(attn_kernel, cudaFuncAttributeMaxDynamicSharedMemorySize, AT_SM);

    __nv_bfloat16 *xh, *xl, *wqh, *wql, *wph, *wpl, *ath, *atl;
    cudaGetSymbolAddress((void**)&xh,  g_x_hi);
    cudaGetSymbolAddress((void**)&xl,  g_x_lo);
    cudaGetSymbolAddress((void**)&wqh, g_wqkv_hi);
    cudaGetSymbolAddress((void**)&wql, g_wqkv_lo);
    cudaGetSymbolAddress((void**)&wph, g_wp_hi);
    cudaGetSymbolAddress((void**)&wpl, g_wp_lo);
    cudaGetSymbolAddress((void**)&ath, g_att_hi);
    cudaGetSymbolAddress((void**)&atl, g_att_lo);

    split_kernel<<<(M_*C_/4 + 255)/256, 256>>>(x, xh, xl, M_*C_/4);
    split_kernel<<<(3*C_*C_/4 + 255)/256, 256>>>(qkv_w, wqh, wql, 3*C_*C_/4);
    split_kernel<<<(C_*C_/4 + 255)/256, 256>>>(proj_w, wph, wpl, C_*C_/4);
    relbias_kernel<<<(NN_ + 255)/256, 256>>>(table, rel_idx);

    gemm5<0><<<dim3(18, 197), 256, GSM_B>>>(xh, xl, wqh, wql, q_bias, v_bias, nullptr);

    attn_kernel<<<dim3(4, H_, B_), 128, AT_SM>>>();

    gemm5<1><<<dim3(6, 197), 256, GSM_B>>>(ath, atl, wph, wpl, proj_b, nullptr, out);
}